// round 12
// baseline (speedup 1.0000x reference)
#include <cuda_runtime.h>
#include <cstdint>

#define NUM_USERS 100000
#define NUM_ITEMS 150000
#define N_NODES   250000
#define DIM       64
#define N_EDGES   2000000
#define EPS_F     0.2f

#define SCAN_B    512
#define N_SCAN_BLK ((N_NODES + SCAN_B - 1) / SCAN_B)   // 489

// ---------------------------------------------------------------------------
// Device scratch (allocation-free, graph-capturable)
// ---------------------------------------------------------------------------
__device__ unsigned g_cnt[N_NODES];        // in-degree per node (build only)
__device__ unsigned g_off[N_NODES + 1];    // CSR row starts (exclusive scan, +sentinel)
__device__ unsigned g_cur[N_NODES];        // fill cursors
__device__ unsigned g_bsum[SCAN_B];        // block sums for the scan
__device__ uint2    g_edges[N_EDGES];      // dst-sorted: {src, val_bits}
__device__ float    g_A[(size_t)N_NODES * DIM];  // x0
__device__ float    g_B[(size_t)N_NODES * DIM];  // x1

// ---------------------------------------------------------------------------
// CSR build
// ---------------------------------------------------------------------------
__global__ void zero_cnt_k() {
    unsigned i = blockIdx.x * blockDim.x + threadIdx.x;
    if (i < N_NODES) { g_cnt[i] = 0u; }
}

__global__ void hist_k(const int* __restrict__ dst) {
    unsigned g = blockIdx.x * blockDim.x + threadIdx.x;
    if (g >= (unsigned)(N_EDGES / 4)) return;
    int4 d4 = __ldg(reinterpret_cast<const int4*>(dst) + g);
    atomicAdd(&g_cnt[d4.x], 1u);
    atomicAdd(&g_cnt[d4.y], 1u);
    atomicAdd(&g_cnt[d4.z], 1u);
    atomicAdd(&g_cnt[d4.w], 1u);
}

__global__ void scan1_k() {
    __shared__ unsigned sm[SCAN_B];
    unsigned i = blockIdx.x * SCAN_B + threadIdx.x;
    unsigned v = (i < N_NODES) ? g_cnt[i] : 0u;
    sm[threadIdx.x] = v;
    __syncthreads();
    for (int ofs = 1; ofs < SCAN_B; ofs <<= 1) {
        unsigned add = (threadIdx.x >= (unsigned)ofs) ? sm[threadIdx.x - ofs] : 0u;
        __syncthreads();
        sm[threadIdx.x] += add;
        __syncthreads();
    }
    unsigned incl = sm[threadIdx.x];
    if (i < N_NODES) g_off[i] = incl - v;            // exclusive within block
    if (threadIdx.x == SCAN_B - 1) g_bsum[blockIdx.x] = incl;
}

__global__ void scan2_k() {
    __shared__ unsigned sm[SCAN_B];
    unsigned v = (threadIdx.x < N_SCAN_BLK) ? g_bsum[threadIdx.x] : 0u;
    sm[threadIdx.x] = v;
    __syncthreads();
    for (int ofs = 1; ofs < SCAN_B; ofs <<= 1) {
        unsigned add = (threadIdx.x >= (unsigned)ofs) ? sm[threadIdx.x - ofs] : 0u;
        __syncthreads();
        sm[threadIdx.x] += add;
        __syncthreads();
    }
    if (threadIdx.x < N_SCAN_BLK) g_bsum[threadIdx.x] = sm[threadIdx.x] - v;  // exclusive
}

__global__ void scan3_k() {
    unsigned i = blockIdx.x * blockDim.x + threadIdx.x;
    if (i >= N_NODES) return;
    unsigned val = g_off[i] + g_bsum[i / SCAN_B];
    g_off[i] = val;
    g_cur[i] = val;
    if (i == 0) g_off[N_NODES] = (unsigned)N_EDGES;   // sentinel
}

__global__ void fill_k(const int* __restrict__ src,
                       const int* __restrict__ dst,
                       const float* __restrict__ vals) {
    unsigned g = blockIdx.x * blockDim.x + threadIdx.x;
    if (g >= (unsigned)(N_EDGES / 4)) return;
    int4   s4 = __ldg(reinterpret_cast<const int4*>(src) + g);
    int4   d4 = __ldg(reinterpret_cast<const int4*>(dst) + g);
    float4 v4 = __ldg(reinterpret_cast<const float4*>(vals) + g);
    unsigned p0 = atomicAdd(&g_cur[d4.x], 1u);
    unsigned p1 = atomicAdd(&g_cur[d4.y], 1u);
    unsigned p2 = atomicAdd(&g_cur[d4.z], 1u);
    unsigned p3 = atomicAdd(&g_cur[d4.w], 1u);
    g_edges[p0] = make_uint2((unsigned)s4.x, __float_as_uint(v4.x));
    g_edges[p1] = make_uint2((unsigned)s4.y, __float_as_uint(v4.y));
    g_edges[p2] = make_uint2((unsigned)s4.z, __float_as_uint(v4.z));
    g_edges[p3] = make_uint2((unsigned)s4.w, __float_as_uint(v4.w));
}

// ---------------------------------------------------------------------------
// Fused layer kernels: gather-reduce + noise perturbation (+ cl / final)
// ONE WARP PER NODE, float2 per lane (32 x 8B = full 256B row).
// No intra-warp degree divergence (all lanes share deg); edge-record loads
// are single-address warp broadcasts; unroll-4 independent gathers.
//   K=0: x0 = f(segsum(E), noise0); A := x0; cl_out = l2norm(x0)
//   K=1: x1 = f(segsum(A), noise1); B := x1
//   K=2: x2 = f(segsum(B), noise2); out = l2norm((e0 + A + B + x2) * 0.25)
// ---------------------------------------------------------------------------
__device__ __forceinline__ float warp_sum(float ss) {
    ss += __shfl_xor_sync(0xffffffffu, ss, 1);
    ss += __shfl_xor_sync(0xffffffffu, ss, 2);
    ss += __shfl_xor_sync(0xffffffffu, ss, 4);
    ss += __shfl_xor_sync(0xffffffffu, ss, 8);
    ss += __shfl_xor_sync(0xffffffffu, ss, 16);
    return ss;
}

template <int K>
__device__ __forceinline__ const float2* src_row(
        unsigned node, const float2* __restrict__ ue, const float2* __restrict__ ie)
{
    if (K == 0) {
        return (node < NUM_USERS) ? (ue + (size_t)node * 32)
                                  : (ie + (size_t)(node - NUM_USERS) * 32);
    }
    const float* b = (K == 1) ? g_A : g_B;
    return reinterpret_cast<const float2*>(b) + (size_t)node * 32;
}

template <int K>
__global__ void __launch_bounds__(256) layer_k(
        const float* __restrict__ noise_k,
        const float2* __restrict__ ue,
        const float2* __restrict__ ie,
        float2* __restrict__ out,      // K==2
        float2* __restrict__ cl_out)   // K==0
{
    unsigned t = blockIdx.x * blockDim.x + threadIdx.x;   // 8M threads exactly
    unsigned node = t >> 5;
    unsigned c = t & 31u;     // float2 column 0..31

    unsigned base = __ldg(&g_off[node]);
    unsigned end  = __ldg(&g_off[node + 1]);
    unsigned deg  = end - base;

    float2 s = make_float2(0.f, 0.f);

    // unroll-4 main loop: 4 independent gathers in flight (uniform across warp)
    unsigned i = 0;
    for (; i + 4 <= deg; i += 4) {
        uint2 e0 = __ldg(&g_edges[base + i]);
        uint2 e1 = __ldg(&g_edges[base + i + 1]);
        uint2 e2 = __ldg(&g_edges[base + i + 2]);
        uint2 e3 = __ldg(&g_edges[base + i + 3]);
        float2 x0 = __ldg(src_row<K>(e0.x, ue, ie) + c);
        float2 x1 = __ldg(src_row<K>(e1.x, ue, ie) + c);
        float2 x2 = __ldg(src_row<K>(e2.x, ue, ie) + c);
        float2 x3 = __ldg(src_row<K>(e3.x, ue, ie) + c);
        float v0 = __uint_as_float(e0.y), v1 = __uint_as_float(e1.y);
        float v2 = __uint_as_float(e2.y), v3 = __uint_as_float(e3.y);
        s.x += v0 * x0.x + v1 * x1.x + v2 * x2.x + v3 * x3.x;
        s.y += v0 * x0.y + v1 * x1.y + v2 * x2.y + v3 * x3.y;
    }
    for (; i < deg; i++) {
        uint2 e = __ldg(&g_edges[base + i]);
        float2 x = __ldg(src_row<K>(e.x, ue, ie) + c);
        float v = __uint_as_float(e.y);
        s.x += v * x.x; s.y += v * x.y;
    }

    // noise perturbation
    float2 n2 = __ldcs(reinterpret_cast<const float2*>(noise_k) + t);
    float ss = warp_sum(n2.x * n2.x + n2.y * n2.y);
    float scale = rsqrtf(fmaxf(ss, 1e-24f)) * EPS_F;

    float2 x = s;
    x.x += (float)((s.x > 0.f) - (s.x < 0.f)) * n2.x * scale;
    x.y += (float)((s.y > 0.f) - (s.y < 0.f)) * n2.y * scale;

    if (K == 2) {
        // fused final: out = l2norm((e0 + x0 + x1 + x2) * 0.25)
        float2 e0 = (node < NUM_USERS)
            ? __ldg(ue + (size_t)node * 32 + c)
            : __ldg(ie + (size_t)(node - NUM_USERS) * 32 + c);
        float2 a0 = reinterpret_cast<const float2*>(g_A)[t];
        float2 a1 = reinterpret_cast<const float2*>(g_B)[t];
        float2 a;
        a.x = (e0.x + a0.x + a1.x + x.x) * 0.25f;
        a.y = (e0.y + a0.y + a1.y + x.y) * 0.25f;
        float s2 = warp_sum(a.x * a.x + a.y * a.y);
        float inv = rsqrtf(fmaxf(s2, 1e-24f));
        a.x *= inv; a.y *= inv;
        __stcs(out + t, a);
        return;
    }

    float2* tgt = (K == 0) ? reinterpret_cast<float2*>(g_A)
                           : reinterpret_cast<float2*>(g_B);
    tgt[t] = x;

    if (K == 0) {
        float s2 = warp_sum(x.x * x.x + x.y * x.y);
        float inv = rsqrtf(fmaxf(s2, 1e-24f));
        x.x *= inv; x.y *= inv;
        __stcs(cl_out + t, x);
    }
}

extern "C" void kernel_launch(void* const* d_in, const int* in_sizes, int n_in,
                              void* d_out, int out_size) {
    const float* user_emb = (const float*)d_in[0];
    const float* item_emb = (const float*)d_in[1];
    const float* vals     = (const float*)d_in[2];
    const float* noise    = (const float*)d_in[3];
    const int*   src      = (const int*)d_in[4];
    const int*   dst      = (const int*)d_in[5];
    float2* out    = (float2*)d_out;
    float2* cl_out = (float2*)((float*)d_out + (size_t)N_NODES * DIM);
    const float2* ue2 = (const float2*)user_emb;
    const float2* ie2 = (const float2*)item_emb;

    const int TB = 256;
    const int node_blk  = (N_NODES + TB - 1) / TB;                 // 977
    const int edge4_blk = (N_EDGES / 4 + TB - 1) / TB;             // 1954
    const int work_blk  = ((unsigned)N_NODES * 32u + TB - 1) / TB; // 31250

    // CSR build
    zero_cnt_k<<<node_blk, TB>>>();
    hist_k<<<edge4_blk, TB>>>(dst);
    scan1_k<<<N_SCAN_BLK, SCAN_B>>>();
    scan2_k<<<1, SCAN_B>>>();
    scan3_k<<<node_blk, TB>>>();
    fill_k<<<edge4_blk, TB>>>(src, dst, vals);

    // fused layers
    layer_k<0><<<work_blk, TB>>>(noise,                              ue2, ie2, out, cl_out);
    layer_k<1><<<work_blk, TB>>>(noise + (size_t)N_NODES * DIM,      ue2, ie2, out, cl_out);
    layer_k<2><<<work_blk, TB>>>(noise + 2 * (size_t)N_NODES * DIM,  ue2, ie2, out, cl_out);
}